// round 1
// baseline (speedup 1.0000x reference)
#include <cuda_runtime.h>
#include <math.h>

#define NB 2
#define NT 2048
#define NC 2048
#define NH 16
#define HD 128
#define NM (NB*NT)      /* 4096 rows */
#define N3C (3*NC)      /* 6144 */

// ---------------- scratch (device globals; no allocations allowed) ----------
__device__ float g_q[(size_t)NB*NH*NT*HD];   // 33.5 MB
__device__ float g_k[(size_t)NB*NH*NT*HD];
__device__ float g_v[(size_t)NB*NH*NT*HD];
__device__ float g_y[(size_t)NM*NC];         // attention output, [B,T,C]

// ---------------- SGEMM: out = A @ W^T + bias -------------------------------
// A: [M,K] row-major, W: [N,K] row-major (both K-contiguous -> NT gemm).
// 128x128x16 tile, 256 threads, 8x8 microtile.
// MODE 0: A=x, W=w_att, scatter into g_q/g_k/g_v ([B,H,T,D])
// MODE 1: A=g_y, W=w_proj, write dense out [M,N]
template<int MODE>
__global__ __launch_bounds__(256)
void sgemm_kernel(const float* __restrict__ Ain, const float* __restrict__ W,
                  const float* __restrict__ bias, float* __restrict__ out)
{
    __shared__ float As[16][132];   // k-major, +4 pad keeps 16B alignment
    __shared__ float Bs[16][132];

    const float* A = (MODE == 1) ? (const float*)g_y : Ain;
    const int K = NC;

    int tid = threadIdx.x;
    int tx = tid & 15, ty = tid >> 4;
    int m0 = blockIdx.y * 128;
    int n0 = blockIdx.x * 128;
    int lrow = tid >> 2;            // 0..63
    int lkv  = (tid & 3) << 2;      // 0,4,8,12

    float acc[8][8];
#pragma unroll
    for (int i = 0; i < 8; i++)
#pragma unroll
        for (int j = 0; j < 8; j++) acc[i][j] = 0.f;

    const float* Ap = A + (size_t)m0 * K + lkv;
    const float* Wp = W + (size_t)n0 * K + lkv;

    for (int k0 = 0; k0 < K; k0 += 16) {
#pragma unroll
        for (int l = 0; l < 2; l++) {
            int r = lrow + l * 64;
            float4 va = *(const float4*)(Ap + (size_t)r * K + k0);
            As[lkv+0][r] = va.x; As[lkv+1][r] = va.y;
            As[lkv+2][r] = va.z; As[lkv+3][r] = va.w;
            float4 vb = *(const float4*)(Wp + (size_t)r * K + k0);
            Bs[lkv+0][r] = vb.x; Bs[lkv+1][r] = vb.y;
            Bs[lkv+2][r] = vb.z; Bs[lkv+3][r] = vb.w;
        }
        __syncthreads();
#pragma unroll
        for (int kk = 0; kk < 16; ++kk) {
            float a[8], b[8];
            *(float4*)&a[0] = *(const float4*)&As[kk][ty*4];
            *(float4*)&a[4] = *(const float4*)&As[kk][64 + ty*4];
            *(float4*)&b[0] = *(const float4*)&Bs[kk][tx*4];
            *(float4*)&b[4] = *(const float4*)&Bs[kk][64 + tx*4];
#pragma unroll
            for (int mi = 0; mi < 8; mi++)
#pragma unroll
                for (int ni = 0; ni < 8; ni++)
                    acc[mi][ni] = fmaf(a[mi], b[ni], acc[mi][ni]);
        }
        __syncthreads();
    }

    if (MODE == 0) {
        // n0 tile (128 wide) lies inside exactly one (q/k/v, head) block
        int which = n0 >> 11;              // 0=q,1=k,2=v
        int h = (n0 & 2047) >> 7;
        float* dst = (which == 0) ? g_q : ((which == 1) ? g_k : g_v);
#pragma unroll
        for (int mi = 0; mi < 8; mi++) {
            int rm = (mi < 4) ? ty*4 + mi : 64 + ty*4 + (mi - 4);
            int m = m0 + rm;
            int bb = m >> 11, t = m & 2047;
            size_t base = (((size_t)bb * NH + h) * NT + t) * HD;
#pragma unroll
            for (int ni = 0; ni < 8; ni++) {
                int rn = (ni < 4) ? tx*4 + ni : 64 + tx*4 + (ni - 4);
                int n = n0 + rn;
                dst[base + (n & 127)] = acc[mi][ni] + bias[n];
            }
        }
    } else {
#pragma unroll
        for (int mi = 0; mi < 8; mi++) {
            int rm = (mi < 4) ? ty*4 + mi : 64 + ty*4 + (mi - 4);
            int m = m0 + rm;
#pragma unroll
            for (int ni = 0; ni < 8; ni++) {
                int rn = (ni < 4) ? tx*4 + ni : 64 + tx*4 + (ni - 4);
                int n = n0 + rn;
                out[(size_t)m * NC + n] = acc[mi][ni] + bias[n];
            }
        }
    }
}

// ---------------- RoPE (in-place on g_q, g_k) --------------------------------
__global__ void rope_kernel()
{
    int idx = blockIdx.x * blockDim.x + threadIdx.x;   // 2 * 65536 * 64 threads
    int pair  = idx & 63;
    int row   = (idx >> 6) & (NB*NH*NT - 1);
    int which = idx >> 22;
    float* buf = which ? g_k : g_q;
    int t = row & (NT - 1);
    float theta = powf(10000.0f, -(float)(2 * pair) * (1.0f / 128.0f));
    float fr = (float)t * theta;
    float s, c;
    sincosf(fr, &s, &c);     // accurate path: args up to ~2047 rad
    size_t off = (size_t)row * 64 + pair;
    float2 v = ((float2*)buf)[off];
    float2 o;
    o.x = v.x * c - v.y * s;
    o.y = v.x * s + v.y * c;
    ((float2*)buf)[off] = o;
}

// ---------------- Flash attention (fp32, causal) -----------------------------
// Block: (bh, qtile). BQ=128, BK=64, 256 threads.
// Scores: 8q x 4k microtile, K in d-major XOR-swizzled smem (conflict-free LDS.128).
// Online softmax (width-16 shuffle), P staged via padded smem, PV 8q x 8d.
#define ATTN_SMEM_FLOATS (128*129 + 128*64 + 64*128 + 128*65)

__global__ __launch_bounds__(256)
void attn_kernel()
{
    extern __shared__ float sm[];
    float* Qs = sm;                 // [128][129] natural, padded
    float* Kt = Qs + 128*129;       // [128][64] d-major, swizzled
    float* Vs = Kt + 128*64;        // [64][128] natural
    float* Ps = Vs + 64*128;        // [128][65] padded

    const int bh = blockIdx.y;
    const int qt = (gridDim.x - 1) - blockIdx.x;  // longest tiles first
    const int q0 = qt * 128;
    const float* Qg = g_q + (size_t)bh * NT * HD;
    const float* Kg = g_k + (size_t)bh * NT * HD;
    const float* Vg = g_v + (size_t)bh * NT * HD;

    int tid = threadIdx.x;
    int tx = tid & 15, ty = tid >> 4;
    const float scale = 0.08838834764831845f;     // 1/sqrt(128)

    // load Q tile (pre-scaled)
    for (int i = tid; i < 128 * 32; i += 256) {
        int q = i >> 5;
        int dv = (i & 31) << 2;
        float4 v = *(const float4*)&Qg[(size_t)(q0 + q) * HD + dv];
        float* qr = Qs + q * 129 + dv;
        qr[0] = v.x * scale; qr[1] = v.y * scale;
        qr[2] = v.z * scale; qr[3] = v.w * scale;
    }

    float o[8][8];
#pragma unroll
    for (int j = 0; j < 8; j++)
#pragma unroll
        for (int d = 0; d < 8; d++) o[j][d] = 0.f;

    float mrow[8], lrow[8];
    int rowi[8];
#pragma unroll
    for (int j = 0; j < 8; j++) {
        mrow[j] = -1e30f; lrow[j] = 0.f;
        rowi[j] = (j < 4) ? ty*4 + j : 64 + ty*4 + (j - 4);
    }

    int ktiles = (qt + 1) * 2;
    for (int kt = 0; kt < ktiles; ++kt) {
        int k0 = kt * 64;
        __syncthreads();   // also covers initial Q-load visibility
        // load K (transposed+swizzled) and V (natural)
        for (int i = tid; i < 64 * 32; i += 256) {
            int kr = i >> 5;
            int dv = (i & 31) << 2;
            float4 vk = *(const float4*)&Kg[(size_t)(k0 + kr) * HD + dv];
            float tmp[4]; *(float4*)tmp = vk;
#pragma unroll
            for (int j = 0; j < 4; j++) {
                int d = dv + j;
                int sw = ((d >> 2) & 15) << 2;
                Kt[d * 64 + (kr ^ sw)] = tmp[j];
            }
            float4 vv = *(const float4*)&Vg[(size_t)(k0 + kr) * HD + dv];
            *(float4*)&Vs[kr * 128 + dv] = vv;
        }
        __syncthreads();

        // ---- scores: S[8][4] ----
        float s_[8][4];
#pragma unroll
        for (int j = 0; j < 8; j++)
#pragma unroll
            for (int c = 0; c < 4; c++) s_[j][c] = 0.f;

#pragma unroll 4
        for (int dd = 0; dd < 128; ++dd) {
            int sw = ((dd >> 2) & 15) << 2;
            float kf[4];
            *(float4*)kf = *(const float4*)&Kt[dd * 64 + ((tx * 4) ^ sw)];
#pragma unroll
            for (int j = 0; j < 8; j++) {
                float qv = Qs[rowi[j] * 129 + dd];
                s_[j][0] = fmaf(qv, kf[0], s_[j][0]);
                s_[j][1] = fmaf(qv, kf[1], s_[j][1]);
                s_[j][2] = fmaf(qv, kf[2], s_[j][2]);
                s_[j][3] = fmaf(qv, kf[3], s_[j][3]);
            }
        }

        // causal mask (only the last two tiles can intersect the diagonal)
        if (k0 + 64 > q0) {
#pragma unroll
            for (int j = 0; j < 8; j++) {
                int qg = q0 + rowi[j];
#pragma unroll
                for (int c = 0; c < 4; c++) {
                    int kg = k0 + tx * 4 + c;
                    if (kg > qg) s_[j][c] = -1e30f;
                }
            }
        }

        // ---- online softmax ----
#pragma unroll
        for (int j = 0; j < 8; j++) {
            float mt = fmaxf(fmaxf(s_[j][0], s_[j][1]), fmaxf(s_[j][2], s_[j][3]));
#pragma unroll
            for (int off = 8; off >= 1; off >>= 1)
                mt = fmaxf(mt, __shfl_xor_sync(0xffffffffu, mt, off, 16));
            float mnew = fmaxf(mrow[j], mt);
            float fac = __expf(mrow[j] - mnew);
            mrow[j] = mnew;
            float rs = 0.f;
            float* prow = Ps + rowi[j] * 65 + tx * 4;
#pragma unroll
            for (int c = 0; c < 4; c++) {
                float p = __expf(s_[j][c] - mnew);
                prow[c] = p;
                rs += p;
            }
#pragma unroll
            for (int off = 8; off >= 1; off >>= 1)
                rs += __shfl_xor_sync(0xffffffffu, rs, off, 16);
            lrow[j] = lrow[j] * fac + rs;
#pragma unroll
            for (int d = 0; d < 8; d++) o[j][d] *= fac;
        }
        __syncthreads();

        // ---- PV: O += P @ V ----
#pragma unroll 2
        for (int kk = 0; kk < 64; ++kk) {
            float vf[8];
            *(float4*)&vf[0] = *(const float4*)&Vs[kk * 128 + tx * 8];
            *(float4*)&vf[4] = *(const float4*)&Vs[kk * 128 + tx * 8 + 4];
#pragma unroll
            for (int j = 0; j < 8; j++) {
                float pv = Ps[rowi[j] * 65 + kk];
#pragma unroll
                for (int d = 0; d < 8; d++)
                    o[j][d] = fmaf(pv, vf[d], o[j][d]);
            }
        }
    }

    // epilogue: O / l  -> g_y in [B,T,C] layout
    int bb = bh >> 4, h = bh & 15;
#pragma unroll
    for (int j = 0; j < 8; j++) {
        float inv = 1.0f / lrow[j];
        int t = q0 + rowi[j];
        size_t base = ((size_t)bb * NT + t) * NC + h * HD + tx * 8;
        float4 w0, w1;
        w0.x = o[j][0]*inv; w0.y = o[j][1]*inv; w0.z = o[j][2]*inv; w0.w = o[j][3]*inv;
        w1.x = o[j][4]*inv; w1.y = o[j][5]*inv; w1.z = o[j][6]*inv; w1.w = o[j][7]*inv;
        *(float4*)&g_y[base]     = w0;
        *(float4*)&g_y[base + 4] = w1;
    }
}

// ---------------- launch ------------------------------------------------------
extern "C" void kernel_launch(void* const* d_in, const int* in_sizes, int n_in,
                              void* d_out, int out_size)
{
    const float* x      = (const float*)d_in[0];
    const float* w_att  = (const float*)d_in[1];
    const float* b_att  = (const float*)d_in[2];
    const float* w_proj = (const float*)d_in[3];
    const float* b_proj = (const float*)d_in[4];
    float* out = (float*)d_out;

    const int attn_smem = ATTN_SMEM_FLOATS * (int)sizeof(float);   // 164,864 B
    cudaFuncSetAttribute(attn_kernel,
                         cudaFuncAttributeMaxDynamicSharedMemorySize, attn_smem);

    // 1) QKV projection + scatter to [B,H,T,D]
    dim3 g1(N3C / 128, NM / 128);   // (48, 32)
    sgemm_kernel<0><<<g1, 256>>>(x, w_att, b_att, nullptr);

    // 2) RoPE in-place on q, k
    rope_kernel<<<(2 * NB * NH * NT * (HD/2)) / 256, 256>>>();

    // 3) causal flash attention -> g_y [B,T,C]
    attn_kernel<<<dim3(NT / 128, NB * NH), 256, attn_smem>>>();

    // 4) output projection -> d_out
    dim3 g2(NC / 128, NM / 128);    // (16, 32)
    sgemm_kernel<1><<<g2, 256>>>(nullptr, w_proj, b_proj, out);
}

// round 4
// speedup vs baseline: 1.6336x; 1.6336x over previous
#include <cuda_runtime.h>
#include <cstdint>
#include <math.h>

#define NB 2
#define NT 2048
#define NC 2048
#define NH 16
#define HD 128
#define NM (NB*NT)      /* 4096 rows */
#define N3C (3*NC)      /* 6144 */

// ---------------- scratch (device globals; no allocations allowed) ----------
__device__ float g_q[(size_t)NB*NH*NT*HD];
__device__ float g_k[(size_t)NB*NH*NT*HD];
__device__ float g_v[(size_t)NB*NH*NT*HD];
__device__ float g_y[(size_t)NM*NC];

// ---------------- helpers ----------------------------------------------------
__device__ __forceinline__ float to_tf32(float x) {
    float r;
    asm("cvt.rna.tf32.f32 %0, %1;" : "=f"(r) : "f"(x));
    return r;
}

// swizzled smem index for a [16][128] k-major tile.
// XOR term uses (k&3)^(k>>2) so BOTH the store phase (k bits 2-3 vary per lane)
// and the mma fragment loads (k bits 0-1 vary per lane) are bank-conflict-free.
__device__ __forceinline__ int swz(int k, int m) {
    return k * 128 + (m ^ ((((k & 3) ^ (k >> 2)) & 3) << 3));
}

__device__ __forceinline__ void mma_tf32(float* c, const uint32_t* a, const uint32_t* b) {
    asm volatile(
        "mma.sync.aligned.m16n8k8.row.col.f32.tf32.tf32.f32 "
        "{%0,%1,%2,%3}, {%4,%5,%6,%7}, {%8,%9}, {%0,%1,%2,%3};"
        : "+f"(c[0]), "+f"(c[1]), "+f"(c[2]), "+f"(c[3])
        : "r"(a[0]), "r"(a[1]), "r"(a[2]), "r"(a[3]), "r"(b[0]), "r"(b[1]));
}

// ---------------- tf32 tensor-core GEMM: out = A @ W^T + bias ----------------
// CTA 128x128, 8 warps (4m x 2n), warp tile 32x64, K-chunk 16 double-buffered.
// MODE 0: A=x, W=w_att -> scatter into g_q/g_k/g_v. MODE 1: A=g_y -> out.
template<int MODE>
__global__ __launch_bounds__(256)
void mgemm_kernel(const float* __restrict__ Ain, const float* __restrict__ W,
                  const float* __restrict__ bias, float* __restrict__ out)
{
    __shared__ float As[2][16 * 128];
    __shared__ float Bs[2][16 * 128];

    const float* A = (MODE == 1) ? (const float*)g_y : Ain;
    const int K = NC;
    const int tid  = threadIdx.x;
    const int lane = tid & 31, wid = tid >> 5;
    const int qrow = lane >> 2, qcol = lane & 3;
    const int wm = (wid & 3) * 32, wn = (wid >> 2) * 64;

    const int m0 = blockIdx.y * 128;
    const int n0 = blockIdx.x * 128;

    const int lrow = tid >> 2;          // 0..63
    const int lk4  = (tid & 3) * 4;     // 0,4,8,12
    const float* Ap = A + (size_t)(m0 + lrow) * K + lk4;
    const float* Wp = W + (size_t)(n0 + lrow) * K + lk4;

    float acc[2][8][4];
#pragma unroll
    for (int i = 0; i < 2; i++)
#pragma unroll
        for (int j = 0; j < 8; j++)
#pragma unroll
            for (int v = 0; v < 4; v++) acc[i][j][v] = 0.f;

    // ---- prologue: stage chunk 0 ----
    {
        float4 va0 = *(const float4*)(Ap);
        float4 va1 = *(const float4*)(Ap + (size_t)64 * K);
        float4 vb0 = *(const float4*)(Wp);
        float4 vb1 = *(const float4*)(Wp + (size_t)64 * K);
        float t[4];
        *(float4*)t = va0;
#pragma unroll
        for (int jj = 0; jj < 4; jj++) As[0][swz(lk4 + jj, lrow)]      = to_tf32(t[jj]);
        *(float4*)t = va1;
#pragma unroll
        for (int jj = 0; jj < 4; jj++) As[0][swz(lk4 + jj, lrow + 64)] = to_tf32(t[jj]);
        *(float4*)t = vb0;
#pragma unroll
        for (int jj = 0; jj < 4; jj++) Bs[0][swz(lk4 + jj, lrow)]      = to_tf32(t[jj]);
        *(float4*)t = vb1;
#pragma unroll
        for (int jj = 0; jj < 4; jj++) Bs[0][swz(lk4 + jj, lrow + 64)] = to_tf32(t[jj]);
    }
    __syncthreads();

    const int NCHU = K / 16;  // 128
    for (int c = 0; c < NCHU; ++c) {
        const int buf = c & 1;
        float4 va0, va1, vb0, vb1;
        if (c + 1 < NCHU) {
            const int k0 = (c + 1) * 16;
            va0 = *(const float4*)(Ap + k0);
            va1 = *(const float4*)(Ap + (size_t)64 * K + k0);
            vb0 = *(const float4*)(Wp + k0);
            vb1 = *(const float4*)(Wp + (size_t)64 * K + k0);
        }

        const float* as = As[buf];
        const float* bs = Bs[buf];
#pragma unroll
        for (int kk = 0; kk < 16; kk += 8) {
            uint32_t afr[2][4];
#pragma unroll
            for (int i = 0; i < 2; i++) {
                const int rb = wm + i * 16;
                afr[i][0] = __float_as_uint(as[swz(kk + qcol,     rb + qrow)]);
                afr[i][1] = __float_as_uint(as[swz(kk + qcol,     rb + qrow + 8)]);
                afr[i][2] = __float_as_uint(as[swz(kk + qcol + 4, rb + qrow)]);
                afr[i][3] = __float_as_uint(as[swz(kk + qcol + 4, rb + qrow + 8)]);
            }
#pragma unroll
            for (int j = 0; j < 8; j++) {
                uint32_t bfr[2];
                const int cb = wn + j * 8 + qrow;
                bfr[0] = __float_as_uint(bs[swz(kk + qcol,     cb)]);
                bfr[1] = __float_as_uint(bs[swz(kk + qcol + 4, cb)]);
                mma_tf32(acc[0][j], afr[0], bfr);
                mma_tf32(acc[1][j], afr[1], bfr);
            }
        }

        if (c + 1 < NCHU) {
            float* at = As[buf ^ 1];
            float* bt = Bs[buf ^ 1];
            float t[4];
            *(float4*)t = va0;
#pragma unroll
            for (int jj = 0; jj < 4; jj++) at[swz(lk4 + jj, lrow)]      = to_tf32(t[jj]);
            *(float4*)t = va1;
#pragma unroll
            for (int jj = 0; jj < 4; jj++) at[swz(lk4 + jj, lrow + 64)] = to_tf32(t[jj]);
            *(float4*)t = vb0;
#pragma unroll
            for (int jj = 0; jj < 4; jj++) bt[swz(lk4 + jj, lrow)]      = to_tf32(t[jj]);
            *(float4*)t = vb1;
#pragma unroll
            for (int jj = 0; jj < 4; jj++) bt[swz(lk4 + jj, lrow + 64)] = to_tf32(t[jj]);
        }
        __syncthreads();
    }

    // ---- epilogue: add bias, store ----
#pragma unroll
    for (int i = 0; i < 2; i++) {
#pragma unroll
        for (int j = 0; j < 8; j++) {
            const int ncol = n0 + wn + j * 8 + (qcol << 1);
            const float b0 = bias[ncol], b1 = bias[ncol + 1];
            const int r0 = m0 + wm + i * 16 + qrow;
            float2 lo = make_float2(acc[i][j][0] + b0, acc[i][j][1] + b1);
            float2 hi = make_float2(acc[i][j][2] + b0, acc[i][j][3] + b1);
            if (MODE == 0) {
                const int which = ncol >> 11;
                const int h = (ncol >> 7) & 15;
                const int d = ncol & 127;
                float* dst = (which == 0) ? g_q : ((which == 1) ? g_k : g_v);
                int bb = r0 >> 11, t0 = r0 & 2047;
                *(float2*)&dst[(((size_t)bb * NH + h) * NT + t0) * HD + d] = lo;
                int r1 = r0 + 8;
                bb = r1 >> 11; t0 = r1 & 2047;
                *(float2*)&dst[(((size_t)bb * NH + h) * NT + t0) * HD + d] = hi;
            } else {
                *(float2*)&out[(size_t)r0 * NC + ncol] = lo;
                *(float2*)&out[(size_t)(r0 + 8) * NC + ncol] = hi;
            }
        }
    }
}

// ---------------- RoPE (in-place on g_q, g_k) --------------------------------
__global__ void rope_kernel()
{
    int idx = blockIdx.x * blockDim.x + threadIdx.x;
    int pair  = idx & 63;
    int row   = (idx >> 6) & (NB*NH*NT - 1);
    int which = idx >> 22;
    float* buf = which ? g_k : g_q;
    int t = row & (NT - 1);
    float theta = powf(10000.0f, -(float)(2 * pair) * (1.0f / 128.0f));
    float fr = (float)t * theta;
    float s, c;
    sincosf(fr, &s, &c);
    size_t off = (size_t)row * 64 + pair;
    float2 v = ((float2*)buf)[off];
    float2 o;
    o.x = v.x * c - v.y * s;
    o.y = v.x * s + v.y * c;
    ((float2*)buf)[off] = o;
}

// ---------------- Flash attention (fp32, causal) -----------------------------
#define ATTN_SMEM_FLOATS (128*129 + 128*64 + 64*128 + 128*65)

__global__ __launch_bounds__(256)
void attn_kernel()
{
    extern __shared__ float sm[];
    float* Qs = sm;                 // [128][129]
    float* Kt = Qs + 128*129;       // [128][64] d-major swizzled
    float* Vs = Kt + 128*64;        // [64][128]
    float* Ps = Vs + 64*128;        // [128][65]

    const int bh = blockIdx.y;
    const int qt = (gridDim.x - 1) - blockIdx.x;
    const int q0 = qt * 128;
    const float* Qg = g_q + (size_t)bh * NT * HD;
    const float* Kg = g_k + (size_t)bh * NT * HD;
    const float* Vg = g_v + (size_t)bh * NT * HD;

    int tid = threadIdx.x;
    int tx = tid & 15, ty = tid >> 4;
    const float scale = 0.08838834764831845f;

    for (int i = tid; i < 128 * 32; i += 256) {
        int q = i >> 5;
        int dv = (i & 31) << 2;
        float4 v = *(const float4*)&Qg[(size_t)(q0 + q) * HD + dv];
        float* qr = Qs + q * 129 + dv;
        qr[0] = v.x * scale; qr[1] = v.y * scale;
        qr[2] = v.z * scale; qr[3] = v.w * scale;
    }

    float o[8][8];
#pragma unroll
    for (int j = 0; j < 8; j++)
#pragma unroll
        for (int d = 0; d < 8; d++) o[j][d] = 0.f;

    float mrow[8], lrow[8];
    int rowi[8];
#pragma unroll
    for (int j = 0; j < 8; j++) {
        mrow[j] = -1e30f; lrow[j] = 0.f;
        rowi[j] = (j < 4) ? ty*4 + j : 64 + ty*4 + (j - 4);
    }

    int ktiles = (qt + 1) * 2;
    for (int kt = 0; kt < ktiles; ++kt) {
        int k0 = kt * 64;
        __syncthreads();
        for (int i = tid; i < 64 * 32; i += 256) {
            int kr = i >> 5;
            int dv = (i & 31) << 2;
            float4 vk = *(const float4*)&Kg[(size_t)(k0 + kr) * HD + dv];
            float tmp[4]; *(float4*)tmp = vk;
#pragma unroll
            for (int j = 0; j < 4; j++) {
                int d = dv + j;
                int sw = ((d >> 2) & 15) << 2;
                Kt[d * 64 + (kr ^ sw)] = tmp[j];
            }
            float4 vv = *(const float4*)&Vg[(size_t)(k0 + kr) * HD + dv];
            *(float4*)&Vs[kr * 128 + dv] = vv;
        }
        __syncthreads();

        float s_[8][4];
#pragma unroll
        for (int j = 0; j < 8; j++)
#pragma unroll
            for (int c = 0; c < 4; c++) s_[j][c] = 0.f;

#pragma unroll 4
        for (int dd = 0; dd < 128; ++dd) {
            int sw = ((dd >> 2) & 15) << 2;
            float kf[4];
            *(float4*)kf = *(const float4*)&Kt[dd * 64 + ((tx * 4) ^ sw)];
#pragma unroll
            for (int j = 0; j < 8; j++) {
                float qv = Qs[rowi[j] * 129 + dd];
                s_[j][0] = fmaf(qv, kf[0], s_[j][0]);
                s_[j][1] = fmaf(qv, kf[1], s_[j][1]);
                s_[j][2] = fmaf(qv, kf[2], s_[j][2]);
                s_[j][3] = fmaf(qv, kf[3], s_[j][3]);
            }
        }

        if (k0 + 64 > q0) {
#pragma unroll
            for (int j = 0; j < 8; j++) {
                int qg = q0 + rowi[j];
#pragma unroll
                for (int c = 0; c < 4; c++) {
                    int kg = k0 + tx * 4 + c;
                    if (kg > qg) s_[j][c] = -1e30f;
                }
            }
        }

#pragma unroll
        for (int j = 0; j < 8; j++) {
            float mt = fmaxf(fmaxf(s_[j][0], s_[j][1]), fmaxf(s_[j][2], s_[j][3]));
#pragma unroll
            for (int off = 8; off >= 1; off >>= 1)
                mt = fmaxf(mt, __shfl_xor_sync(0xffffffffu, mt, off, 16));
            float mnew = fmaxf(mrow[j], mt);
            float fac = __expf(mrow[j] - mnew);
            mrow[j] = mnew;
            float rs = 0.f;
            float* prow = Ps + rowi[j] * 65 + tx * 4;
#pragma unroll
            for (int c = 0; c < 4; c++) {
                float p = __expf(s_[j][c] - mnew);
                prow[c] = p;
                rs += p;
            }
#pragma unroll
            for (int off = 8; off >= 1; off >>= 1)
                rs += __shfl_xor_sync(0xffffffffu, rs, off, 16);
            lrow[j] = lrow[j] * fac + rs;
#pragma unroll
            for (int d = 0; d < 8; d++) o[j][d] *= fac;
        }
        __syncthreads();

#pragma unroll 2
        for (int kk = 0; kk < 64; ++kk) {
            float vf[8];
            *(float4*)&vf[0] = *(const float4*)&Vs[kk * 128 + tx * 8];
            *(float4*)&vf[4] = *(const float4*)&Vs[kk * 128 + tx * 8 + 4];
#pragma unroll
            for (int j = 0; j < 8; j++) {
                float pv = Ps[rowi[j] * 65 + kk];
#pragma unroll
                for (int d = 0; d < 8; d++)
                    o[j][d] = fmaf(pv, vf[d], o[j][d]);
            }
        }
    }

    int bb = bh >> 4, h = bh & 15;
#pragma unroll
    for (int j = 0; j < 8; j++) {
        float inv = 1.0f / lrow[j];
        int t = q0 + rowi[j];
        size_t base = ((size_t)bb * NT + t) * NC + h * HD + tx * 8;
        float4 w0, w1;
        w0.x = o[j][0]*inv; w0.y = o[j][1]*inv; w0.z = o[j][2]*inv; w0.w = o[j][3]*inv;
        w1.x = o[j][4]*inv; w1.y = o[j][5]*inv; w1.z = o[j][6]*inv; w1.w = o[j][7]*inv;
        *(float4*)&g_y[base]     = w0;
        *(float4*)&g_y[base + 4] = w1;
    }
}

// ---------------- launch ------------------------------------------------------
extern "C" void kernel_launch(void* const* d_in, const int* in_sizes, int n_in,
                              void* d_out, int out_size)
{
    const float* x      = (const float*)d_in[0];
    const float* w_att  = (const float*)d_in[1];
    const float* b_att  = (const float*)d_in[2];
    const float* w_proj = (const float*)d_in[3];
    const float* b_proj = (const float*)d_in[4];
    float* out = (float*)d_out;

    const int attn_smem = ATTN_SMEM_FLOATS * (int)sizeof(float);
    cudaFuncSetAttribute(attn_kernel,
                         cudaFuncAttributeMaxDynamicSharedMemorySize, attn_smem);

    // 1) QKV projection (tf32 mma.sync) + scatter to [B,H,T,D]
    dim3 g1(N3C / 128, NM / 128);   // (48, 32)
    mgemm_kernel<0><<<g1, 256>>>(x, w_att, b_att, nullptr);

    // 2) RoPE in-place on q, k
    rope_kernel<<<(2 * NB * NH * NT * (HD/2)) / 256, 256>>>();

    // 3) causal flash attention -> g_y [B,T,C]
    attn_kernel<<<dim3(NT / 128, NB * NH), 256, attn_smem>>>();

    // 4) output projection (tf32 mma.sync) -> d_out
    dim3 g2(NC / 128, NM / 128);    // (16, 32)
    mgemm_kernel<1><<<g2, 256>>>(nullptr, w_proj, b_proj, out);
}

// round 5
// speedup vs baseline: 2.0207x; 1.2370x over previous
#include <cuda_runtime.h>
#include <cstdint>
#include <math.h>

#define NB 2
#define NT 2048
#define NC 2048
#define NH 16
#define HD 128
#define NM (NB*NT)      /* 4096 rows */
#define N3C (3*NC)      /* 6144 */

// ---------------- scratch (device globals; no allocations allowed) ----------
__device__ float g_q[(size_t)NB*NH*NT*HD];
__device__ float g_k[(size_t)NB*NH*NT*HD];
__device__ float g_v[(size_t)NB*NH*NT*HD];
__device__ float g_y[(size_t)NM*NC];

// ---------------- helpers ----------------------------------------------------
__device__ __forceinline__ float to_tf32(float x) {
    float r;
    asm("cvt.rna.tf32.f32 %0, %1;" : "=f"(r) : "f"(x));
    return r;
}
__device__ __forceinline__ uint32_t smem_u32(const void* p) {
    uint32_t a;
    asm("{ .reg .u64 t; cvta.to.shared.u64 t, %1; cvt.u32.u64 %0, t; }"
        : "=r"(a) : "l"(p));
    return a;
}
__device__ __forceinline__ void cpasync16(uint32_t s, const void* g) {
    asm volatile("cp.async.ca.shared.global [%0], [%1], 16;" :: "r"(s), "l"(g));
}
#define CP_COMMIT()  asm volatile("cp.async.commit_group;" ::: "memory")
#define CP_WAIT1()   asm volatile("cp.async.wait_group 1;" ::: "memory")

// swizzled smem index for a [16][128] k-major tile (GEMM staging).
__device__ __forceinline__ int swz(int k, int m) {
    return k * 128 + (m ^ ((((k & 3) ^ (k >> 2)) & 3) << 3));
}

__device__ __forceinline__ void mma_tf32(float* c, const uint32_t* a, const uint32_t* b) {
    asm volatile(
        "mma.sync.aligned.m16n8k8.row.col.f32.tf32.tf32.f32 "
        "{%0,%1,%2,%3}, {%4,%5,%6,%7}, {%8,%9}, {%0,%1,%2,%3};"
        : "+f"(c[0]), "+f"(c[1]), "+f"(c[2]), "+f"(c[3])
        : "r"(a[0]), "r"(a[1]), "r"(a[2]), "r"(a[3]), "r"(b[0]), "r"(b[1]));
}

// fast exp for x <= 0: FMA/ALU pipes only (no MUFU, no CVT).
__device__ __forceinline__ float fexp(float x) {
    float t = fmaxf(x * 1.442695041f, -126.0f);
    float r = t + 12582912.0f;            // round-to-nearest integer (magic)
    float i = r - 12582912.0f;
    float f = t - i;                      // [-0.5, 0.5]
    float p =              1.3333558e-3f;
    p = fmaf(p, f, 9.6181291e-3f);
    p = fmaf(p, f, 5.5504109e-2f);
    p = fmaf(p, f, 2.4022651e-1f);
    p = fmaf(p, f, 6.9314718e-1f);
    p = fmaf(p, f, 1.0f);
    int sb = (__float_as_int(r) << 23) + 0x3F800000;
    return p * __int_as_float(sb);
}

// ---------------- tf32 tensor-core GEMM: out = A @ W^T + bias ----------------
template<int MODE>
__global__ __launch_bounds__(256)
void mgemm_kernel(const float* __restrict__ Ain, const float* __restrict__ W,
                  const float* __restrict__ bias, float* __restrict__ out)
{
    __shared__ float As[2][16 * 128];
    __shared__ float Bs[2][16 * 128];

    const float* A = (MODE == 1) ? (const float*)g_y : Ain;
    const int K = NC;
    const int tid  = threadIdx.x;
    const int lane = tid & 31, wid = tid >> 5;
    const int qrow = lane >> 2, qcol = lane & 3;
    const int wm = (wid & 3) * 32, wn = (wid >> 2) * 64;

    const int m0 = blockIdx.y * 128;
    const int n0 = blockIdx.x * 128;

    const int lrow = tid >> 2;
    const int lk4  = (tid & 3) * 4;
    const float* Ap = A + (size_t)(m0 + lrow) * K + lk4;
    const float* Wp = W + (size_t)(n0 + lrow) * K + lk4;

    float acc[2][8][4];
#pragma unroll
    for (int i = 0; i < 2; i++)
#pragma unroll
        for (int j = 0; j < 8; j++)
#pragma unroll
            for (int v = 0; v < 4; v++) acc[i][j][v] = 0.f;

    {
        float4 va0 = *(const float4*)(Ap);
        float4 va1 = *(const float4*)(Ap + (size_t)64 * K);
        float4 vb0 = *(const float4*)(Wp);
        float4 vb1 = *(const float4*)(Wp + (size_t)64 * K);
        float t[4];
        *(float4*)t = va0;
#pragma unroll
        for (int jj = 0; jj < 4; jj++) As[0][swz(lk4 + jj, lrow)]      = to_tf32(t[jj]);
        *(float4*)t = va1;
#pragma unroll
        for (int jj = 0; jj < 4; jj++) As[0][swz(lk4 + jj, lrow + 64)] = to_tf32(t[jj]);
        *(float4*)t = vb0;
#pragma unroll
        for (int jj = 0; jj < 4; jj++) Bs[0][swz(lk4 + jj, lrow)]      = to_tf32(t[jj]);
        *(float4*)t = vb1;
#pragma unroll
        for (int jj = 0; jj < 4; jj++) Bs[0][swz(lk4 + jj, lrow + 64)] = to_tf32(t[jj]);
    }
    __syncthreads();

    const int NCHU = K / 16;
    for (int c = 0; c < NCHU; ++c) {
        const int buf = c & 1;
        float4 va0, va1, vb0, vb1;
        if (c + 1 < NCHU) {
            const int k0 = (c + 1) * 16;
            va0 = *(const float4*)(Ap + k0);
            va1 = *(const float4*)(Ap + (size_t)64 * K + k0);
            vb0 = *(const float4*)(Wp + k0);
            vb1 = *(const float4*)(Wp + (size_t)64 * K + k0);
        }

        const float* as = As[buf];
        const float* bs = Bs[buf];
#pragma unroll
        for (int kk = 0; kk < 16; kk += 8) {
            uint32_t afr[2][4];
#pragma unroll
            for (int i = 0; i < 2; i++) {
                const int rb = wm + i * 16;
                afr[i][0] = __float_as_uint(as[swz(kk + qcol,     rb + qrow)]);
                afr[i][1] = __float_as_uint(as[swz(kk + qcol,     rb + qrow + 8)]);
                afr[i][2] = __float_as_uint(as[swz(kk + qcol + 4, rb + qrow)]);
                afr[i][3] = __float_as_uint(as[swz(kk + qcol + 4, rb + qrow + 8)]);
            }
#pragma unroll
            for (int j = 0; j < 8; j++) {
                uint32_t bfr[2];
                const int cb = wn + j * 8 + qrow;
                bfr[0] = __float_as_uint(bs[swz(kk + qcol,     cb)]);
                bfr[1] = __float_as_uint(bs[swz(kk + qcol + 4, cb)]);
                mma_tf32(acc[0][j], afr[0], bfr);
                mma_tf32(acc[1][j], afr[1], bfr);
            }
        }

        if (c + 1 < NCHU) {
            float* at = As[buf ^ 1];
            float* bt = Bs[buf ^ 1];
            float t[4];
            *(float4*)t = va0;
#pragma unroll
            for (int jj = 0; jj < 4; jj++) at[swz(lk4 + jj, lrow)]      = to_tf32(t[jj]);
            *(float4*)t = va1;
#pragma unroll
            for (int jj = 0; jj < 4; jj++) at[swz(lk4 + jj, lrow + 64)] = to_tf32(t[jj]);
            *(float4*)t = vb0;
#pragma unroll
            for (int jj = 0; jj < 4; jj++) bt[swz(lk4 + jj, lrow)]      = to_tf32(t[jj]);
            *(float4*)t = vb1;
#pragma unroll
            for (int jj = 0; jj < 4; jj++) bt[swz(lk4 + jj, lrow + 64)] = to_tf32(t[jj]);
        }
        __syncthreads();
    }

    // ---- epilogue: add bias, store (v pre-rounded to tf32 for attention) ----
#pragma unroll
    for (int i = 0; i < 2; i++) {
#pragma unroll
        for (int j = 0; j < 8; j++) {
            const int ncol = n0 + wn + j * 8 + (qcol << 1);
            const float b0 = bias[ncol], b1 = bias[ncol + 1];
            const int r0 = m0 + wm + i * 16 + qrow;
            float2 lo = make_float2(acc[i][j][0] + b0, acc[i][j][1] + b1);
            float2 hi = make_float2(acc[i][j][2] + b0, acc[i][j][3] + b1);
            if (MODE == 0) {
                const int which = ncol >> 11;
                const int h = (ncol >> 7) & 15;
                const int d = ncol & 127;
                float* dst = (which == 0) ? g_q : ((which == 1) ? g_k : g_v);
                if (which == 2) {
                    lo.x = to_tf32(lo.x); lo.y = to_tf32(lo.y);
                    hi.x = to_tf32(hi.x); hi.y = to_tf32(hi.y);
                }
                int bb = r0 >> 11, t0 = r0 & 2047;
                *(float2*)&dst[(((size_t)bb * NH + h) * NT + t0) * HD + d] = lo;
                int r1 = r0 + 8;
                bb = r1 >> 11; t0 = r1 & 2047;
                *(float2*)&dst[(((size_t)bb * NH + h) * NT + t0) * HD + d] = hi;
            } else {
                *(float2*)&out[(size_t)r0 * NC + ncol] = lo;
                *(float2*)&out[(size_t)(r0 + 8) * NC + ncol] = hi;
            }
        }
    }
}

// ---------------- RoPE (in-place; q pre-scaled by 1/sqrt(D); tf32-rounded) ---
__global__ void rope_kernel()
{
    int idx = blockIdx.x * blockDim.x + threadIdx.x;
    int pair  = idx & 63;
    int row   = (idx >> 6) & (NB*NH*NT - 1);
    int which = idx >> 22;
    float* buf = which ? g_k : g_q;
    int t = row & (NT - 1);
    float theta = powf(10000.0f, -(float)(2 * pair) * (1.0f / 128.0f));
    float fr = (float)t * theta;
    float s, c;
    sincosf(fr, &s, &c);
    size_t off = (size_t)row * 64 + pair;
    float2 v = ((float2*)buf)[off];
    float ox = v.x * c - v.y * s;
    float oy = v.x * s + v.y * c;
    if (which == 0) {   // q: fold in softmax scale
        const float scale = 0.08838834764831845f;
        ox *= scale; oy *= scale;
    }
    float2 o;
    o.x = to_tf32(ox);
    o.y = to_tf32(oy);
    ((float2*)buf)[off] = o;
}

// ---------------- Flash attention (tf32 mma, causal) -------------------------
// BQ=128, BK=64, 8 warps; warp w owns q rows [16w,16w+16).
// Smem strides chosen conflict-free for all fragment access patterns.
#define AQS 132
#define AKS 132
#define AVS 136
#define APS 76
#define OFF_Q 0
#define OFF_K (128*AQS)                 /* 16896 */
#define OFF_V (OFF_K + 2*64*AKS)        /* 33792 */
#define OFF_P (OFF_V + 64*AVS)          /* 42496 */
#define ATTN_FLOATS (OFF_P + 128*APS)   /* 52224 -> 208896 B */

__global__ __launch_bounds__(256)
void attn_kernel()
{
    extern __shared__ float sm[];
    const uint32_t sb = smem_u32(sm);
    const int tid = threadIdx.x;
    const int lane = tid & 31, w = tid >> 5;
    const int qrow = lane >> 2, qcol = lane & 3;
    const int bh = blockIdx.y;
    const int qt = (gridDim.x - 1) - blockIdx.x;
    const int q0 = qt * 128;
    const float* Qg = g_q + (size_t)bh * NT * HD + (size_t)q0 * HD;
    const float* Kg = g_k + (size_t)bh * NT * HD;
    const float* Vg = g_v + (size_t)bh * NT * HD;

    // group 1: Q tile + K tile 0
    for (int c = tid; c < 128 * 32; c += 256) {
        int row = c >> 5, ch = (c & 31) * 4;
        cpasync16(sb + (uint32_t)(OFF_Q + row * AQS + ch) * 4, Qg + (size_t)row * HD + ch);
    }
    for (int c = tid; c < 64 * 32; c += 256) {
        int row = c >> 5, ch = (c & 31) * 4;
        cpasync16(sb + (uint32_t)(OFF_K + row * AKS + ch) * 4, Kg + (size_t)row * HD + ch);
    }
    CP_COMMIT();
    // group 2: V tile 0
    for (int c = tid; c < 64 * 32; c += 256) {
        int row = c >> 5, ch = (c & 31) * 4;
        cpasync16(sb + (uint32_t)(OFF_V + row * AVS + ch) * 4, Vg + (size_t)row * HD + ch);
    }
    CP_COMMIT();

    float o[16][4];
#pragma unroll
    for (int jd = 0; jd < 16; jd++)
#pragma unroll
        for (int v = 0; v < 4; v++) o[jd][v] = 0.f;
    float m0 = -1e30f, m1 = -1e30f, l0 = 0.f, l1 = 0.f;
    const int r_lo = 16 * w + qrow;

    const float* qs = sm + OFF_Q + (16 * w) * AQS;
    float* psw = sm + OFF_P + (16 * w) * APS;

    const int nkt = (qt + 1) * 2;
    for (int kt = 0; kt < nkt; ++kt) {
        const int k0 = kt * 64;
        const int kb = kt & 1;

        CP_WAIT1();            // K[kt] (and Q on kt==0) complete
        __syncthreads();

        // prefetch K[kt+1]
        if (kt + 1 < nkt) {
            const float* Kn = Kg + (size_t)(k0 + 64) * HD;
            uint32_t kdst = sb + (uint32_t)(OFF_K + (kb ^ 1) * 64 * AKS) * 4;
            for (int c = tid; c < 64 * 32; c += 256) {
                int row = c >> 5, ch = (c & 31) * 4;
                cpasync16(kdst + (uint32_t)(row * AKS + ch) * 4, Kn + (size_t)row * HD + ch);
            }
        }
        CP_COMMIT();

        // ---- QK^T: s[8][4], warp tile m16 x n64, K over d=128 ----
        float s[8][4];
#pragma unroll
        for (int j = 0; j < 8; j++)
#pragma unroll
            for (int v = 0; v < 4; v++) s[j][v] = 0.f;

        const float* ks = sm + OFF_K + kb * 64 * AKS;
#pragma unroll
        for (int kk = 0; kk < 16; ++kk) {
            const int kc = kk * 8;
            uint32_t a[4];
            a[0] = __float_as_uint(qs[qrow * AQS + kc + qcol]);
            a[1] = __float_as_uint(qs[(qrow + 8) * AQS + kc + qcol]);
            a[2] = __float_as_uint(qs[qrow * AQS + kc + qcol + 4]);
            a[3] = __float_as_uint(qs[(qrow + 8) * AQS + kc + qcol + 4]);
#pragma unroll
            for (int j = 0; j < 8; j++) {
                uint32_t b[2];
                b[0] = __float_as_uint(ks[(8 * j + qrow) * AKS + kc + qcol]);
                b[1] = __float_as_uint(ks[(8 * j + qrow) * AKS + kc + qcol + 4]);
                mma_tf32(s[j], a, b);
            }
        }

        // ---- causal mask ----
        if (k0 + 64 > q0) {
            const int row0 = q0 + r_lo;
#pragma unroll
            for (int j = 0; j < 8; j++) {
                const int key = k0 + 8 * j + 2 * qcol;
                if (key     > row0)     s[j][0] = -1e30f;
                if (key + 1 > row0)     s[j][1] = -1e30f;
                if (key     > row0 + 8) s[j][2] = -1e30f;
                if (key + 1 > row0 + 8) s[j][3] = -1e30f;
            }
        }

        // ---- online softmax (2 rows per lane) ----
        float mx0 = -1e30f, mx1 = -1e30f;
#pragma unroll
        for (int j = 0; j < 8; j++) {
            mx0 = fmaxf(mx0, fmaxf(s[j][0], s[j][1]));
            mx1 = fmaxf(mx1, fmaxf(s[j][2], s[j][3]));
        }
        mx0 = fmaxf(mx0, __shfl_xor_sync(0xffffffffu, mx0, 1));
        mx0 = fmaxf(mx0, __shfl_xor_sync(0xffffffffu, mx0, 2));
        mx1 = fmaxf(mx1, __shfl_xor_sync(0xffffffffu, mx1, 1));
        mx1 = fmaxf(mx1, __shfl_xor_sync(0xffffffffu, mx1, 2));
        const float mn0 = fmaxf(m0, mx0), mn1 = fmaxf(m1, mx1);
        const float fac0 = fexp(m0 - mn0), fac1 = fexp(m1 - mn1);
        m0 = mn0; m1 = mn1;

        float sum0 = 0.f, sum1 = 0.f;
#pragma unroll
        for (int j = 0; j < 8; j++) {
            float p00 = fexp(s[j][0] - mn0);
            float p01 = fexp(s[j][1] - mn0);
            float p10 = fexp(s[j][2] - mn1);
            float p11 = fexp(s[j][3] - mn1);
            sum0 += p00 + p01;
            sum1 += p10 + p11;
            *(float2*)&psw[qrow * APS + 8 * j + 2 * qcol] =
                make_float2(to_tf32(p00), to_tf32(p01));
            *(float2*)&psw[(qrow + 8) * APS + 8 * j + 2 * qcol] =
                make_float2(to_tf32(p10), to_tf32(p11));
        }
        sum0 += __shfl_xor_sync(0xffffffffu, sum0, 1);
        sum0 += __shfl_xor_sync(0xffffffffu, sum0, 2);
        sum1 += __shfl_xor_sync(0xffffffffu, sum1, 1);
        sum1 += __shfl_xor_sync(0xffffffffu, sum1, 2);
        l0 = l0 * fac0 + sum0;
        l1 = l1 * fac1 + sum1;

#pragma unroll
        for (int jd = 0; jd < 16; jd++) {
            o[jd][0] *= fac0; o[jd][1] *= fac0;
            o[jd][2] *= fac1; o[jd][3] *= fac1;
        }
        __syncwarp();

        // ---- PV: O += P @ V ----
        CP_WAIT1();            // V[kt] complete (K[kt+1] may fly)
        __syncthreads();

        const float* vs = sm + OFF_V;
#pragma unroll
        for (int kk = 0; kk < 8; ++kk) {
            const int kc = kk * 8;
            uint32_t a[4];
            a[0] = __float_as_uint(psw[qrow * APS + kc + qcol]);
            a[1] = __float_as_uint(psw[(qrow + 8) * APS + kc + qcol]);
            a[2] = __float_as_uint(psw[qrow * APS + kc + qcol + 4]);
            a[3] = __float_as_uint(psw[(qrow + 8) * APS + kc + qcol + 4]);
#pragma unroll
            for (int jd = 0; jd < 16; jd++) {
                uint32_t b[2];
                b[0] = __float_as_uint(vs[(kc + qcol) * AVS + 8 * jd + qrow]);
                b[1] = __float_as_uint(vs[(kc + qcol + 4) * AVS + 8 * jd + qrow]);
                mma_tf32(o[jd], a, b);
            }
        }

        __syncthreads();       // all warps done reading Vs

        // prefetch V[kt+1]
        if (kt + 1 < nkt) {
            const float* Vn = Vg + (size_t)(k0 + 64) * HD;
            for (int c = tid; c < 64 * 32; c += 256) {
                int row = c >> 5, ch = (c & 31) * 4;
                cpasync16(sb + (uint32_t)(OFF_V + row * AVS + ch) * 4, Vn + (size_t)row * HD + ch);
            }
            CP_COMMIT();
        }
    }

    // ---- epilogue: O / l -> g_y [B,T,C] ----
    const float il0 = 1.0f / l0, il1 = 1.0f / l1;
    const int bb = bh >> 4, h = bh & 15;
    const int t0g = q0 + r_lo;
    float* y0 = g_y + ((size_t)bb * NT + t0g) * NC + h * HD;
    float* y1 = g_y + ((size_t)bb * NT + t0g + 8) * NC + h * HD;
#pragma unroll
    for (int jd = 0; jd < 16; jd++) {
        const int d = 8 * jd + 2 * qcol;
        *(float2*)&y0[d] = make_float2(o[jd][0] * il0, o[jd][1] * il0);
        *(float2*)&y1[d] = make_float2(o[jd][2] * il1, o[jd][3] * il1);
    }
}

// ---------------- launch ------------------------------------------------------
extern "C" void kernel_launch(void* const* d_in, const int* in_sizes, int n_in,
                              void* d_out, int out_size)
{
    const float* x      = (const float*)d_in[0];
    const float* w_att  = (const float*)d_in[1];
    const float* b_att  = (const float*)d_in[2];
    const float* w_proj = (const float*)d_in[3];
    const float* b_proj = (const float*)d_in[4];
    float* out = (float*)d_out;

    const int attn_smem = ATTN_FLOATS * (int)sizeof(float);   // 208,896 B
    cudaFuncSetAttribute(attn_kernel,
                         cudaFuncAttributeMaxDynamicSharedMemorySize, attn_smem);

    // 1) QKV projection (tf32 mma.sync) + scatter to [B,H,T,D]
    dim3 g1(N3C / 128, NM / 128);   // (48, 32)
    mgemm_kernel<0><<<g1, 256>>>(x, w_att, b_att, nullptr);

    // 2) RoPE in-place on q, k (q pre-scaled; both tf32-rounded)
    rope_kernel<<<(2 * NB * NH * NT * (HD/2)) / 256, 256>>>();

    // 3) causal flash attention (tf32 mma) -> g_y [B,T,C]
    attn_kernel<<<dim3(NT / 128, NB * NH), 256, attn_smem>>>();

    // 4) output projection (tf32 mma.sync) -> d_out
    dim3 g2(NC / 128, NM / 128);    // (16, 32)
    mgemm_kernel<1><<<g2, 256>>>(nullptr, w_proj, b_proj, out);
}

// round 6
// speedup vs baseline: 2.8467x; 1.4087x over previous
#include <cuda_runtime.h>
#include <cstdint>
#include <math.h>

#define NB 2
#define NT 2048
#define NC 2048
#define NH 16
#define HD 128
#define NM (NB*NT)      /* 4096 rows */
#define N3C (3*NC)      /* 6144 */

// ---------------- scratch (device globals; no allocations allowed) ----------
__device__ float g_q[(size_t)NB*NH*NT*HD];
__device__ float g_k[(size_t)NB*NH*NT*HD];
__device__ float g_v[(size_t)NB*NH*NT*HD];
__device__ float g_y[(size_t)NM*NC];
__device__ float g_xr[(size_t)NM*NC];       // tf32-rounded x
__device__ float g_war[(size_t)N3C*NC];     // tf32-rounded w_att
__device__ float g_wpr[(size_t)NC*NC];      // tf32-rounded w_proj

// ---------------- helpers ----------------------------------------------------
__device__ __forceinline__ float to_tf32(float x) {
    float r;
    asm("cvt.rna.tf32.f32 %0, %1;" : "=f"(r) : "f"(x));
    return r;
}
__device__ __forceinline__ uint32_t smem_u32(const void* p) {
    uint32_t a;
    asm("{ .reg .u64 t; cvta.to.shared.u64 t, %1; cvt.u32.u64 %0, t; }"
        : "=r"(a) : "l"(p));
    return a;
}
__device__ __forceinline__ void cpasync16(uint32_t s, const void* g) {
    asm volatile("cp.async.cg.shared.global [%0], [%1], 16;" :: "r"(s), "l"(g));
}
#define CP_COMMIT()  asm volatile("cp.async.commit_group;" ::: "memory")
#define CP_WAIT1()   asm volatile("cp.async.wait_group 1;" ::: "memory")

__device__ __forceinline__ void mma_tf32(float* c, const uint32_t* a, const uint32_t* b) {
    asm volatile(
        "mma.sync.aligned.m16n8k8.row.col.f32.tf32.tf32.f32 "
        "{%0,%1,%2,%3}, {%4,%5,%6,%7}, {%8,%9}, {%0,%1,%2,%3};"
        : "+f"(c[0]), "+f"(c[1]), "+f"(c[2]), "+f"(c[3])
        : "r"(a[0]), "r"(a[1]), "r"(a[2]), "r"(a[3]), "r"(b[0]), "r"(b[1]));
}

// fast exp for x <= 0: FMA/ALU pipes only.
__device__ __forceinline__ float fexp(float x) {
    float t = fmaxf(x * 1.442695041f, -126.0f);
    float r = t + 12582912.0f;
    float i = r - 12582912.0f;
    float f = t - i;
    float p =              1.3333558e-3f;
    p = fmaf(p, f, 9.6181291e-3f);
    p = fmaf(p, f, 5.5504109e-2f);
    p = fmaf(p, f, 2.4022651e-1f);
    p = fmaf(p, f, 6.9314718e-1f);
    p = fmaf(p, f, 1.0f);
    int sb = (__float_as_int(r) << 23) + 0x3F800000;
    return p * __int_as_float(sb);
}

// ---------------- pre-round inputs to tf32 (RNA) ------------------------------
__global__ void round_kernel(const float* __restrict__ in, float* __restrict__ out, int n4)
{
    int i = blockIdx.x * blockDim.x + threadIdx.x;
    if (i < n4) {
        float4 v = ((const float4*)in)[i];
        v.x = to_tf32(v.x); v.y = to_tf32(v.y);
        v.z = to_tf32(v.z); v.w = to_tf32(v.w);
        ((float4*)out)[i] = v;
    }
}

// ---------------- tf32 tensor-core GEMM v2: out = A @ W^T + bias --------------
// CTA 256(M) x 128(N), 8 warps as 4m x 2n of 64x64 warp tiles.
// cp.async 3-stage pipeline, K-chunk 16, smem row stride 20 (conflict-free).
// MODE 0: A=g_xr, W=g_war -> scatter to g_q/g_k/g_v. MODE 1: A=g_y, W=g_wpr -> out.
#define ASTRIDE 20
#define A_ST_FL (256*ASTRIDE)                 /* 5120 */
#define B_ST_FL (128*ASTRIDE)                 /* 2560 */
#define ST_FL   (A_ST_FL + B_ST_FL)           /* 7680 floats = 30720 B */
#define NSTAGE  3
#define GEMM_SMEM (NSTAGE*ST_FL*4)            /* 92160 B */

template<int MODE>
__global__ __launch_bounds__(256, 1)
void mgemm2_kernel(const float* __restrict__ bias, float* __restrict__ out)
{
    extern __shared__ float sm2[];
    const float* A = (MODE == 1) ? (const float*)g_y : (const float*)g_xr;
    const float* W = (MODE == 1) ? (const float*)g_wpr : (const float*)g_war;
    const int K = NC;

    const int tid = threadIdx.x;
    const int lane = tid & 31, wid = tid >> 5;
    const int qr = lane >> 2, qc = lane & 3;
    const int wm = (wid >> 1) * 64;
    const int wn = (wid & 1) * 64;
    const int m0 = blockIdx.y * 256;
    const int n0 = blockIdx.x * 128;

    // staging mapping: thread -> row tid>>2 (+64*l), 16B chunk (tid&3)
    const int srow = tid >> 2;
    const int sch  = (tid & 3) * 4;
    const float* Ag = A + (size_t)(m0 + srow) * K + sch;
    const float* Wg = W + (size_t)(n0 + srow) * K + sch;
    const uint32_t sm_base = smem_u32(sm2);
    const uint32_t a_sm = sm_base + (uint32_t)(srow * ASTRIDE + sch) * 4;
    const uint32_t b_sm = a_sm + A_ST_FL * 4;

    float acc[4][8][4];
#pragma unroll
    for (int i = 0; i < 4; i++)
#pragma unroll
        for (int j = 0; j < 8; j++)
#pragma unroll
            for (int v = 0; v < 4; v++) acc[i][j][v] = 0.f;

    const int NCHU = K / 16;   // 128

    // prologue: stages 0, 1
#pragma unroll
    for (int s = 0; s < 2; s++) {
        const int k0 = s * 16;
        const uint32_t so = (uint32_t)(s * ST_FL) * 4;
#pragma unroll
        for (int l = 0; l < 4; l++)
            cpasync16(a_sm + so + (uint32_t)(l * 64 * ASTRIDE) * 4,
                      Ag + (size_t)l * 64 * K + k0);
#pragma unroll
        for (int l = 0; l < 2; l++)
            cpasync16(b_sm + so + (uint32_t)(l * 64 * ASTRIDE) * 4,
                      Wg + (size_t)l * 64 * K + k0);
        CP_COMMIT();
    }

    int stage = 0;        // stage index of chunk c
    int nstage = 2;       // stage index of chunk c+2
#pragma unroll 1
    for (int c = 0; c < NCHU; ++c) {
        CP_WAIT1();
        __syncthreads();

        // issue chunk c+2 into nstage
        if (c + 2 < NCHU) {
            const int k0 = (c + 2) * 16;
            const uint32_t so = (uint32_t)(nstage * ST_FL) * 4;
#pragma unroll
            for (int l = 0; l < 4; l++)
                cpasync16(a_sm + so + (uint32_t)(l * 64 * ASTRIDE) * 4,
                          Ag + (size_t)l * 64 * K + k0);
#pragma unroll
            for (int l = 0; l < 2; l++)
                cpasync16(b_sm + so + (uint32_t)(l * 64 * ASTRIDE) * 4,
                          Wg + (size_t)l * 64 * K + k0);
        }
        CP_COMMIT();

        // compute chunk c
        const float* as = sm2 + stage * ST_FL;
        const float* bs = as + A_ST_FL;
#pragma unroll
        for (int kk = 0; kk < 16; kk += 8) {
            uint32_t af[4][4];
#pragma unroll
            for (int i = 0; i < 4; i++) {
                const float* ap = as + (wm + i * 16 + qr) * ASTRIDE + kk + qc;
                af[i][0] = __float_as_uint(ap[0]);
                af[i][1] = __float_as_uint(ap[8 * ASTRIDE]);
                af[i][2] = __float_as_uint(ap[4]);
                af[i][3] = __float_as_uint(ap[8 * ASTRIDE + 4]);
            }
#pragma unroll
            for (int j = 0; j < 8; j++) {
                uint32_t bf[2];
                const float* bp = bs + (wn + j * 8 + qr) * ASTRIDE + kk + qc;
                bf[0] = __float_as_uint(bp[0]);
                bf[1] = __float_as_uint(bp[4]);
#pragma unroll
                for (int i = 0; i < 4; i++)
                    mma_tf32(acc[i][j], af[i], bf);
            }
        }

        stage = (stage == NSTAGE - 1) ? 0 : stage + 1;
        nstage = (nstage == NSTAGE - 1) ? 0 : nstage + 1;
    }

    // ---- epilogue: add bias, store ----
#pragma unroll
    for (int i = 0; i < 4; i++) {
#pragma unroll
        for (int j = 0; j < 8; j++) {
            const int ncol = n0 + wn + j * 8 + (qc << 1);
            const float b0 = bias[ncol], b1 = bias[ncol + 1];
            const int r0 = m0 + wm + i * 16 + qr;
            float2 lo = make_float2(acc[i][j][0] + b0, acc[i][j][1] + b1);
            float2 hi = make_float2(acc[i][j][2] + b0, acc[i][j][3] + b1);
            if (MODE == 0) {
                const int which = ncol >> 11;
                const int h = (ncol >> 7) & 15;
                const int d = ncol & 127;
                float* dst = (which == 0) ? g_q : ((which == 1) ? g_k : g_v);
                if (which == 2) {   // v feeds tf32 MMA directly: pre-round
                    lo.x = to_tf32(lo.x); lo.y = to_tf32(lo.y);
                    hi.x = to_tf32(hi.x); hi.y = to_tf32(hi.y);
                }
                int bb = r0 >> 11, t0 = r0 & 2047;
                *(float2*)&dst[(((size_t)bb * NH + h) * NT + t0) * HD + d] = lo;
                const int r1 = r0 + 8;
                bb = r1 >> 11; t0 = r1 & 2047;
                *(float2*)&dst[(((size_t)bb * NH + h) * NT + t0) * HD + d] = hi;
            } else {
                *(float2*)&out[(size_t)r0 * NC + ncol] = lo;
                *(float2*)&out[(size_t)(r0 + 8) * NC + ncol] = hi;
            }
        }
    }
}

// ---------------- RoPE (in-place; q pre-scaled by 1/sqrt(D); tf32-rounded) ---
__global__ void rope_kernel()
{
    int idx = blockIdx.x * blockDim.x + threadIdx.x;
    int pair  = idx & 63;
    int row   = (idx >> 6) & (NB*NH*NT - 1);
    int which = idx >> 22;
    float* buf = which ? g_k : g_q;
    int t = row & (NT - 1);
    float theta = powf(10000.0f, -(float)(2 * pair) * (1.0f / 128.0f));
    float fr = (float)t * theta;
    float s, c;
    sincosf(fr, &s, &c);
    size_t off = (size_t)row * 64 + pair;
    float2 v = ((float2*)buf)[off];
    float ox = v.x * c - v.y * s;
    float oy = v.x * s + v.y * c;
    if (which == 0) {
        const float scale = 0.08838834764831845f;
        ox *= scale; oy *= scale;
    }
    float2 o;
    o.x = to_tf32(ox);
    o.y = to_tf32(oy);
    ((float2*)buf)[off] = o;
}

// ---------------- Flash attention (tf32 mma, causal) -------------------------
#define AQS 132
#define AKS 132
#define AVS 136
#define APS 76
#define OFF_Q 0
#define OFF_K (128*AQS)
#define OFF_V (OFF_K + 2*64*AKS)
#define OFF_P (OFF_V + 64*AVS)
#define ATTN_FLOATS (OFF_P + 128*APS)

__global__ __launch_bounds__(256)
void attn_kernel()
{
    extern __shared__ float sm[];
    const uint32_t sb = smem_u32(sm);
    const int tid = threadIdx.x;
    const int lane = tid & 31, w = tid >> 5;
    const int qrow = lane >> 2, qcol = lane & 3;
    const int bh = blockIdx.y;
    const int qt = (gridDim.x - 1) - blockIdx.x;
    const int q0 = qt * 128;
    const float* Qg = g_q + (size_t)bh * NT * HD + (size_t)q0 * HD;
    const float* Kg = g_k + (size_t)bh * NT * HD;
    const float* Vg = g_v + (size_t)bh * NT * HD;

    for (int c = tid; c < 128 * 32; c += 256) {
        int row = c >> 5, ch = (c & 31) * 4;
        asm volatile("cp.async.ca.shared.global [%0], [%1], 16;"
            :: "r"(sb + (uint32_t)(OFF_Q + row * AQS + ch) * 4),
               "l"(Qg + (size_t)row * HD + ch));
    }
    for (int c = tid; c < 64 * 32; c += 256) {
        int row = c >> 5, ch = (c & 31) * 4;
        asm volatile("cp.async.ca.shared.global [%0], [%1], 16;"
            :: "r"(sb + (uint32_t)(OFF_K + row * AKS + ch) * 4),
               "l"(Kg + (size_t)row * HD + ch));
    }
    CP_COMMIT();
    for (int c = tid; c < 64 * 32; c += 256) {
        int row = c >> 5, ch = (c & 31) * 4;
        asm volatile("cp.async.ca.shared.global [%0], [%1], 16;"
            :: "r"(sb + (uint32_t)(OFF_V + row * AVS + ch) * 4),
               "l"(Vg + (size_t)row * HD + ch));
    }
    CP_COMMIT();

    float o[16][4];
#pragma unroll
    for (int jd = 0; jd < 16; jd++)
#pragma unroll
        for (int v = 0; v < 4; v++) o[jd][v] = 0.f;
    float m0 = -1e30f, m1 = -1e30f, l0 = 0.f, l1 = 0.f;
    const int r_lo = 16 * w + qrow;

    const float* qs = sm + OFF_Q + (16 * w) * AQS;
    float* psw = sm + OFF_P + (16 * w) * APS;

    const int nkt = (qt + 1) * 2;
    for (int kt = 0; kt < nkt; ++kt) {
        const int k0 = kt * 64;
        const int kb = kt & 1;

        CP_WAIT1();
        __syncthreads();

        if (kt + 1 < nkt) {
            const float* Kn = Kg + (size_t)(k0 + 64) * HD;
            uint32_t kdst = sb + (uint32_t)(OFF_K + (kb ^ 1) * 64 * AKS) * 4;
            for (int c = tid; c < 64 * 32; c += 256) {
                int row = c >> 5, ch = (c & 31) * 4;
                asm volatile("cp.async.ca.shared.global [%0], [%1], 16;"
                    :: "r"(kdst + (uint32_t)(row * AKS + ch) * 4),
                       "l"(Kn + (size_t)row * HD + ch));
            }
        }
        CP_COMMIT();

        float s[8][4];
#pragma unroll
        for (int j = 0; j < 8; j++)
#pragma unroll
            for (int v = 0; v < 4; v++) s[j][v] = 0.f;

        const float* ks = sm + OFF_K + kb * 64 * AKS;
#pragma unroll
        for (int kk = 0; kk < 16; ++kk) {
            const int kc = kk * 8;
            uint32_t a[4];
            a[0] = __float_as_uint(qs[qrow * AQS + kc + qcol]);
            a[1] = __float_as_uint(qs[(qrow + 8) * AQS + kc + qcol]);
            a[2] = __float_as_uint(qs[qrow * AQS + kc + qcol + 4]);
            a[3] = __float_as_uint(qs[(qrow + 8) * AQS + kc + qcol + 4]);
#pragma unroll
            for (int j = 0; j < 8; j++) {
                uint32_t b[2];
                b[0] = __float_as_uint(ks[(8 * j + qrow) * AKS + kc + qcol]);
                b[1] = __float_as_uint(ks[(8 * j + qrow) * AKS + kc + qcol + 4]);
                mma_tf32(s[j], a, b);
            }
        }

        if (k0 + 64 > q0) {
            const int row0 = q0 + r_lo;
#pragma unroll
            for (int j = 0; j < 8; j++) {
                const int key = k0 + 8 * j + 2 * qcol;
                if (key     > row0)     s[j][0] = -1e30f;
                if (key + 1 > row0)     s[j][1] = -1e30f;
                if (key     > row0 + 8) s[j][2] = -1e30f;
                if (key + 1 > row0 + 8) s[j][3] = -1e30f;
            }
        }

        float mx0 = -1e30f, mx1 = -1e30f;
#pragma unroll
        for (int j = 0; j < 8; j++) {
            mx0 = fmaxf(mx0, fmaxf(s[j][0], s[j][1]));
            mx1 = fmaxf(mx1, fmaxf(s[j][2], s[j][3]));
        }
        mx0 = fmaxf(mx0, __shfl_xor_sync(0xffffffffu, mx0, 1));
        mx0 = fmaxf(mx0, __shfl_xor_sync(0xffffffffu, mx0, 2));
        mx1 = fmaxf(mx1, __shfl_xor_sync(0xffffffffu, mx1, 1));
        mx1 = fmaxf(mx1, __shfl_xor_sync(0xffffffffu, mx1, 2));
        const float mn0 = fmaxf(m0, mx0), mn1 = fmaxf(m1, mx1);
        const float fac0 = fexp(m0 - mn0), fac1 = fexp(m1 - mn1);
        m0 = mn0; m1 = mn1;

        float sum0 = 0.f, sum1 = 0.f;
#pragma unroll
        for (int j = 0; j < 8; j++) {
            float p00 = fexp(s[j][0] - mn0);
            float p01 = fexp(s[j][1] - mn0);
            float p10 = fexp(s[j][2] - mn1);
            float p11 = fexp(s[j][3] - mn1);
            sum0 += p00 + p01;
            sum1 += p10 + p11;
            *(float2*)&psw[qrow * APS + 8 * j + 2 * qcol] =
                make_float2(to_tf32(p00), to_tf32(p01));
            *(float2*)&psw[(qrow + 8) * APS + 8 * j + 2 * qcol] =
                make_float2(to_tf32(p10), to_tf32(p11));
        }
        sum0 += __shfl_xor_sync(0xffffffffu, sum0, 1);
        sum0 += __shfl_xor_sync(0xffffffffu, sum0, 2);
        sum1 += __shfl_xor_sync(0xffffffffu, sum1, 1);
        sum1 += __shfl_xor_sync(0xffffffffu, sum1, 2);
        l0 = l0 * fac0 + sum0;
        l1 = l1 * fac1 + sum1;

#pragma unroll
        for (int jd = 0; jd < 16; jd++) {
            o[jd][0] *= fac0; o[jd][1] *= fac0;
            o[jd][2] *= fac1; o[jd][3] *= fac1;
        }
        __syncwarp();

        CP_WAIT1();
        __syncthreads();

        const float* vs = sm + OFF_V;
#pragma unroll
        for (int kk = 0; kk < 8; ++kk) {
            const int kc = kk * 8;
            uint32_t a[4];
            a[0] = __float_as_uint(psw[qrow * APS + kc + qcol]);
            a[1] = __float_as_uint(psw[(qrow + 8) * APS + kc + qcol]);
            a[2] = __float_as_uint(psw[qrow * APS + kc + qcol + 4]);
            a[3] = __float_as_uint(psw[(qrow + 8) * APS + kc + qcol + 4]);
#pragma unroll
            for (int jd = 0; jd < 16; jd++) {
                uint32_t b[2];
                b[0] = __float_as_uint(vs[(kc + qcol) * AVS + 8 * jd + qrow]);
                b[1] = __float_as_uint(vs[(kc + qcol + 4) * AVS + 8 * jd + qrow]);
                mma_tf32(o[jd], a, b);
            }
        }

        __syncthreads();

        if (kt + 1 < nkt) {
            const float* Vn = Vg + (size_t)(k0 + 64) * HD;
            for (int c = tid; c < 64 * 32; c += 256) {
                int row = c >> 5, ch = (c & 31) * 4;
                asm volatile("cp.async.ca.shared.global [%0], [%1], 16;"
                    :: "r"(sb + (uint32_t)(OFF_V + row * AVS + ch) * 4),
                       "l"(Vn + (size_t)row * HD + ch));
            }
            CP_COMMIT();
        }
    }

    // epilogue: O / l -> g_y [B,T,C], pre-rounded to tf32 for the proj GEMM
    const float il0 = 1.0f / l0, il1 = 1.0f / l1;
    const int bb = bh >> 4, h = bh & 15;
    const int t0g = q0 + r_lo;
    float* y0 = g_y + ((size_t)bb * NT + t0g) * NC + h * HD;
    float* y1 = g_y + ((size_t)bb * NT + t0g + 8) * NC + h * HD;
#pragma unroll
    for (int jd = 0; jd < 16; jd++) {
        const int d = 8 * jd + 2 * qcol;
        *(float2*)&y0[d] = make_float2(to_tf32(o[jd][0] * il0), to_tf32(o[jd][1] * il0));
        *(float2*)&y1[d] = make_float2(to_tf32(o[jd][2] * il1), to_tf32(o[jd][3] * il1));
    }
}

// ---------------- launch ------------------------------------------------------
extern "C" void kernel_launch(void* const* d_in, const int* in_sizes, int n_in,
                              void* d_out, int out_size)
{
    const float* x      = (const float*)d_in[0];
    const float* w_att  = (const float*)d_in[1];
    const float* b_att  = (const float*)d_in[2];
    const float* w_proj = (const float*)d_in[3];
    const float* b_proj = (const float*)d_in[4];
    float* out = (float*)d_out;

    cudaFuncSetAttribute(mgemm2_kernel<0>,
                         cudaFuncAttributeMaxDynamicSharedMemorySize, GEMM_SMEM);
    cudaFuncSetAttribute(mgemm2_kernel<1>,
                         cudaFuncAttributeMaxDynamicSharedMemorySize, GEMM_SMEM);
    const int attn_smem = ATTN_FLOATS * (int)sizeof(float);
    cudaFuncSetAttribute(attn_kernel,
                         cudaFuncAttributeMaxDynamicSharedMemorySize, attn_smem);

    // 0) pre-round inputs to tf32 (RNA) scratch copies
    float* d_xr;  cudaGetSymbolAddress((void**)&d_xr,  g_xr);
    float* d_war; cudaGetSymbolAddress((void**)&d_war, g_war);
    float* d_wpr; cudaGetSymbolAddress((void**)&d_wpr, g_wpr);
    round_kernel<<<(NM*NC/4 + 255)/256, 256>>>(x, d_xr, NM*NC/4);
    round_kernel<<<(N3C*NC/4 + 255)/256, 256>>>(w_att, d_war, N3C*NC/4);
    round_kernel<<<(NC*NC/4 + 255)/256, 256>>>(w_proj, d_wpr, NC*NC/4);

    // 1) QKV projection (tf32 mma, cp.async pipeline) + scatter to [B,H,T,D]
    dim3 g1(N3C / 128, NM / 256);   // (48, 16)
    mgemm2_kernel<0><<<g1, 256, GEMM_SMEM>>>(b_att, nullptr);

    // 2) RoPE in-place on q, k
    rope_kernel<<<(2 * NB * NH * NT * (HD/2)) / 256, 256>>>();

    // 3) causal flash attention (tf32 mma) -> g_y [B,T,C]
    attn_kernel<<<dim3(NT / 128, NB * NH), 256, attn_smem>>>();

    // 4) output projection -> d_out
    dim3 g2(NC / 128, NM / 256);    // (16, 16)
    mgemm2_kernel<1><<<g2, 256, GEMM_SMEM>>>(b_proj, out);
}